// round 7
// baseline (speedup 1.0000x reference)
#include <cuda_runtime.h>
#include <cuda_fp16.h>
#include <math.h>
#include <stdint.h>

#define NPTS   30000
#define NV     4
#define SNB    6
#define PTILE  16
#define MROWS  128
#define TILES_MAIN 1875
#define GRIDX  37
#define EP_ROWS 128
#define EP_TILES 235

typedef unsigned long long ull;

// ---------------- device scratch (allocation-free) ----------------
__device__ __align__(16) unsigned char g_Mt[NV * 131072];   // M^T fp16, swizzled [n][k] 512B rows
__device__ __align__(16) unsigned char g_Ang[NV * 98304];   // A1ng^T fp16, swizzled [h][i] 384B rows
__device__ float    g_C[NV * 256];
__device__ uint32_t g_ep[NV * NPTS * 128];                  // enc_pre half2 pairs

// ---------------- helpers ----------------
__device__ __forceinline__ uint32_t smem_u32(const void* p) {
    uint32_t a;
    asm("{ .reg .u64 t; cvta.to.shared.u64 t, %1; cvt.u32.u64 %0, t; }" : "=r"(a) : "l"(p));
    return a;
}
__device__ __forceinline__ void ldsm_x4(uint32_t r[4], uint32_t addr) {
    asm volatile("ldmatrix.sync.aligned.m8n8.x4.shared.b16 {%0,%1,%2,%3}, [%4];"
                 : "=r"(r[0]), "=r"(r[1]), "=r"(r[2]), "=r"(r[3]) : "r"(addr));
}
__device__ __forceinline__ void ldsm_x2(uint32_t& r0, uint32_t& r1, uint32_t addr) {
    asm volatile("ldmatrix.sync.aligned.m8n8.x2.shared.b16 {%0,%1}, [%2];"
                 : "=r"(r0), "=r"(r1) : "r"(addr));
}
__device__ __forceinline__ void mma_16816(float c[4], const uint32_t a[4],
                                          uint32_t b0, uint32_t b1) {
    asm volatile("mma.sync.aligned.m16n8k16.row.col.f32.f16.f16.f32 "
                 "{%0,%1,%2,%3}, {%4,%5,%6,%7}, {%8,%9}, {%0,%1,%2,%3};"
                 : "+f"(c[0]), "+f"(c[1]), "+f"(c[2]), "+f"(c[3])
                 : "r"(a[0]), "r"(a[1]), "r"(a[2]), "r"(a[3]), "r"(b0), "r"(b1));
}
__device__ __forceinline__ ull pk2(float x, float y) {
    ull r; asm("mov.b64 %0, {%1, %2};" : "=l"(r) : "f"(x), "f"(y)); return r;
}
__device__ __forceinline__ void unpk2(ull p, float& x, float& y) {
    asm("mov.b64 {%0, %1}, %2;" : "=f"(x), "=f"(y) : "l"(p));
}
__device__ __forceinline__ void fma2(ull& d, ull a, ull b) {
    asm("fma.rn.f32x2 %0, %1, %2, %0;" : "+l"(d) : "l"(a), "l"(b));
}
__device__ __forceinline__ uint32_t f22u(float a, float b) {
    __half2 h = __floats2half2_rn(a, b);
    return *reinterpret_cast<uint32_t*>(&h);
}
__device__ __forceinline__ void cp16(uint32_t dst, const void* src) {
    asm volatile("cp.async.cg.shared.global [%0], [%1], 16;" :: "r"(dst), "l"(src));
}
__device__ __forceinline__ void cp_commit() { asm volatile("cp.async.commit_group;" ::: "memory"); }
__device__ __forceinline__ void cp_wait0()  { asm volatile("cp.async.wait_group 0;" ::: "memory"); }

// swizzled byte offsets: 16B-unit index XOR (row&7)
__device__ __forceinline__ uint32_t swz512(int r, int k) {   // 256 halves per row
    return (uint32_t)(r * 512 + ((((k >> 3) ^ (r & 7))) << 4) + (k & 7) * 2);
}
__device__ __forceinline__ uint32_t swz384(int r, int k) {   // 192 halves per row
    return (uint32_t)(r * 384 + ((((k >> 3) ^ (r & 7))) << 4) + (k & 7) * 2);
}

// ---------------- precompute kernels ----------------
__global__ void precompute_Mt(const float* __restrict__ W2, const float* __restrict__ A1) {
    int v = blockIdx.y, k = blockIdx.x, n = threadIdx.x;   // M[k][n]
    __shared__ float w2row[128];
    if (threadIdx.x < 128) w2row[threadIdx.x] = W2[(v * 256 + k) * 128 + threadIdx.x];
    __syncthreads();
    const float* a1 = A1 + (v * 320) * 256 + n;
    float acc = 0.f;
#pragma unroll 8
    for (int o = 0; o < 128; o++) acc += w2row[o] * a1[o * 256];
    *(__half*)(g_Mt + v * 131072 + swz512(n, k)) = __float2half(acc);
}

__global__ void precompute_C(const float* __restrict__ b2, const float* __restrict__ A1,
                             const float* __restrict__ Ab1) {
    int v = blockIdx.x, h = threadIdx.x;
    __shared__ float b2s[128];
    if (threadIdx.x < 128) b2s[threadIdx.x] = b2[v * 128 + threadIdx.x];
    __syncthreads();
    float acc = Ab1[v * 256 + h];
#pragma unroll 8
    for (int o = 0; o < 128; o++) acc += b2s[o] * A1[(v * 320 + o) * 256 + h];
    g_C[v * 256 + h] = acc;
}

__global__ void precompute_Ang(const float* __restrict__ A1) {
    int b = blockIdx.x;           // NV*192
    int v = b / 192, i = b % 192, h = threadIdx.x;
    *(__half*)(g_Ang + v * 98304 + swz384(h, i)) =
        __float2half(A1[(v * 320 + 128 + i) * 256 + h]);
}

// ---------------- ep prepass ----------------
#define E_B 0
#define E_A 98304
#define E_C 147456
#define EP_SMEM 148480

__global__ void __launch_bounds__(1024, 1)
ep_kernel(const float* __restrict__ encN, const float* __restrict__ encG) {
    extern __shared__ unsigned char smem[];
    const uint32_t sb = smem_u32(smem);
    const int tid = threadIdx.x, wid = tid >> 5, lane = tid & 31;
    const int v = blockIdx.y;
    const int wm = wid & 3, wn = wid >> 2;       // 4 m-warps x 8 n-warps, tile 32x32

    { // B copy (swizzle-preserving)
        const float4* src = (const float4*)(g_Ang + v * 98304);
        float4* dst = (float4*)(smem + E_B);
        for (int i = tid; i < 6144; i += 1024) dst[i] = src[i];
    }
    float* sC = (float*)(smem + E_C);
    if (tid < 256) sC[tid] = g_C[v * 256 + tid];
    __syncthreads();

    const int arow0 = wm * 32 + (lane & 15), arow1 = arow0 + 16;
    const uint32_t aT0 = sb + E_A + arow0 * 384, aC0 = (uint32_t)(arow0 & 7) << 4;
    const uint32_t aT1 = sb + E_A + arow1 * 384, aC1 = (uint32_t)(arow1 & 7) << 4;
    const uint32_t s16 = (uint32_t)(lane >> 4) * 16;
    uint32_t bT[4], bC[4];
#pragma unroll
    for (int nt = 0; nt < 4; nt++) {
        int brow = wn * 32 + nt * 8 + (lane & 7);
        bT[nt] = sb + E_B + brow * 384;
        bC[nt] = (uint32_t)(brow & 7) << 4;
    }
    const uint32_t bs16 = (uint32_t)((lane >> 3) & 1) * 16;
    const int l4 = lane >> 2, l2 = (lane & 3) * 2;

    for (int t = blockIdx.x; t < EP_TILES; t += GRIDX) {
        const int n0 = t * EP_ROWS;
        for (int i = tid; i < 12288; i += 1024) {
            int r = i / 96, kk = (i % 96) * 2, n = n0 + r;
            float e0 = 0.f, e1 = 0.f;
            if (n < NPTS) {
                if (kk < 128) { e0 = encN[n * 128 + kk];      e1 = encN[n * 128 + kk + 1]; }
                else          { e0 = encG[n * 64 + kk - 128]; e1 = encG[n * 64 + kk - 127]; }
            }
            *(uint32_t*)(smem + E_A + swz384(r, kk)) = f22u(e0, e1);
        }
        __syncthreads();

        float acc[2][4][4];
#pragma unroll
        for (int mt = 0; mt < 2; mt++)
#pragma unroll
            for (int nt = 0; nt < 4; nt++)
#pragma unroll
                for (int q = 0; q < 4; q++) acc[mt][nt][q] = 0.f;

#pragma unroll
        for (int ks = 0; ks < 12; ks++) {
            uint32_t a0[4], a1[4];
            ldsm_x4(a0, aT0 + (((uint32_t)ks * 32 + s16) ^ aC0));
            ldsm_x4(a1, aT1 + (((uint32_t)ks * 32 + s16) ^ aC1));
#pragma unroll
            for (int nt = 0; nt < 4; nt++) {
                uint32_t b0, b1;
                ldsm_x2(b0, b1, bT[nt] + (((uint32_t)ks * 32 + bs16) ^ bC[nt]));
                mma_16816(acc[0][nt], a0, b0, b1);
                mma_16816(acc[1][nt], a1, b0, b1);
            }
        }

#pragma unroll
        for (int mt = 0; mt < 2; mt++)
#pragma unroll
            for (int x = 0; x < 2; x++) {
                int row = wm * 32 + mt * 16 + x * 8 + l4;
                int n = n0 + row;
                if (n < NPTS) {
                    uint32_t* dst = &g_ep[(v * NPTS + n) * 128];
#pragma unroll
                    for (int nt = 0; nt < 4; nt++) {
                        int col = wn * 32 + nt * 8 + l2;
                        dst[col >> 1] = f22u(acc[mt][nt][2 * x] + sC[col],
                                             acc[mt][nt][2 * x + 1] + sC[col + 1]);
                    }
                }
            }
        __syncthreads();
    }
}

// ---------------- main fused kernel ----------------
#define M_B   0
#define M_A   131072
#define M_EP  196608          // 2 x 8192
#define M_W1  212992
#define M_B1  220160
#define M_A2  221184
#define M_XF  222208
#define M_INV 226304
#define M_ROW 226816
#define MAIN_SMEM 230912

__global__ void __launch_bounds__(1024, 1)
main_kernel(const float* __restrict__ centers,  const float* __restrict__ nbrs,
            const float* __restrict__ norms,    const float* __restrict__ nbrnorms,
            const float* __restrict__ areas,    const float* __restrict__ nbrareas,
            const float* __restrict__ W1,       const float* __restrict__ b1,
            const float* __restrict__ A2,       const float* __restrict__ Ab2,
            float* __restrict__ out) {
    extern __shared__ unsigned char smem[];
    const uint32_t sb = smem_u32(smem);
    const int tid = threadIdx.x, wid = tid >> 5, lane = tid & 31;
    const int v = blockIdx.y;
    const int wm = wid & 3, wn = wid >> 2;       // 4 m-warps x 8 n-warps

    float* sW1  = (float*)(smem + M_W1);
    float* sB1  = (float*)(smem + M_B1);
    float* sA2  = (float*)(smem + M_A2);
    float* sXF  = (float*)(smem + M_XF);
    float* sInv = (float*)(smem + M_INV);
    float* sRow = (float*)(smem + M_ROW);

    { // resident B = M^T (128 KB, swizzled)
        const float4* src = (const float4*)(g_Mt + v * 131072);
        float4* dst = (float4*)(smem + M_B);
        for (int i = tid; i < 8192; i += 1024) dst[i] = src[i];
    }
    if (tid < 256) { sA2[tid] = A2[v * 256 + tid]; sB1[tid] = b1[v * 256 + tid]; }
    for (int i = tid; i < 7 * 256; i += 1024) sW1[i] = W1[v * 7 * 256 + i];
    const float Ab2v = Ab2[v];

    // ---- prologue: stage xf + ep for first tile ----
    const int t0 = blockIdx.x;
    if (tid < MROWS) {
        const int p = tid >> 3, i = tid & 7, n = t0 * PTILE + p;
        float f[7];
        if (i == 0) {
            f[0] = centers[n * 3 + 0]; f[1] = centers[n * 3 + 1]; f[2] = centers[n * 3 + 2];
            f[3] = norms[n * 3 + 0];   f[4] = norms[n * 3 + 1];   f[5] = norms[n * 3 + 2];
            f[6] = __logf(areas[n]) * 0.1f;
        } else if (i < 7) {
            int s = i - 1, base = (n * SNB + s) * 3;
            f[0] = nbrs[base + 0] + 1e-6f;     f[1] = nbrs[base + 1] + 1e-6f;     f[2] = nbrs[base + 2] + 1e-6f;
            f[3] = nbrnorms[base + 0] + 1e-6f; f[4] = nbrnorms[base + 1] + 1e-6f; f[5] = nbrnorms[base + 2] + 1e-6f;
            f[6] = __logf(nbrareas[n * SNB + s]) * 0.1f + 1e-6f;
        } else {
#pragma unroll
            for (int j = 0; j < 7; j++) f[j] = 0.f;
        }
#pragma unroll
        for (int j = 0; j < 7; j++) sXF[tid * 8 + j] = f[j];
        sXF[tid * 8 + 7] = 0.f;
    }
    if (tid < 512)
        cp16(sb + M_EP + tid * 16,
             (const unsigned char*)g_ep + (size_t)(v * NPTS + t0 * PTILE) * 512 + tid * 16);
    cp_commit();
    cp_wait0();
    __syncthreads();

    // lane-constant LDSM address terms
    const int arow0 = wm * 32 + (lane & 15), arow1 = arow0 + 16;
    const uint32_t aT0 = sb + M_A + arow0 * 512, aC0 = (uint32_t)(arow0 & 7) << 4;
    const uint32_t aT1 = sb + M_A + arow1 * 512, aC1 = (uint32_t)(arow1 & 7) << 4;
    const uint32_t s16 = (uint32_t)(lane >> 4) * 16;
    uint32_t bT[4], bC[4];
#pragma unroll
    for (int nt = 0; nt < 4; nt++) {
        int brow = wn * 32 + nt * 8 + (lane & 7);
        bT[nt] = sb + M_B + brow * 512;
        bC[nt] = (uint32_t)(brow & 7) << 4;
    }
    const uint32_t bs16 = (uint32_t)((lane >> 3) & 1) * 16;
    const int l4 = lane >> 2, l2 = (lane & 3) * 2;

    int ping = 0;
    for (int t = t0; t < TILES_MAIN; t += GRIDX) {
        const int n0 = t * PTILE;
        const int tn = t + GRIDX;
        const bool nv_ok = (tn < TILES_MAIN);

        // ---- prefetch next tile: features -> regs, ep -> cp.async into other buffer ----
        float f[7];
        if (tid < MROWS && nv_ok) {
            const int p = tid >> 3, i = tid & 7, n = tn * PTILE + p;
            if (i == 0) {
                f[0] = centers[n * 3 + 0]; f[1] = centers[n * 3 + 1]; f[2] = centers[n * 3 + 2];
                f[3] = norms[n * 3 + 0];   f[4] = norms[n * 3 + 1];   f[5] = norms[n * 3 + 2];
                f[6] = __logf(areas[n]) * 0.1f;
            } else if (i < 7) {
                int s = i - 1, base = (n * SNB + s) * 3;
                f[0] = nbrs[base + 0] + 1e-6f;     f[1] = nbrs[base + 1] + 1e-6f;     f[2] = nbrs[base + 2] + 1e-6f;
                f[3] = nbrnorms[base + 0] + 1e-6f; f[4] = nbrnorms[base + 1] + 1e-6f; f[5] = nbrnorms[base + 2] + 1e-6f;
                f[6] = __logf(nbrareas[n * SNB + s]) * 0.1f + 1e-6f;
            } else {
#pragma unroll
                for (int j = 0; j < 7; j++) f[j] = 0.f;
            }
        }
        if (tid < 512 && nv_ok)
            cp16(sb + M_EP + (ping ^ 1) * 8192 + tid * 16,
                 (const unsigned char*)g_ep + (size_t)(v * NPTS + tn * PTILE) * 512 + tid * 16);
        cp_commit();

        // ---- inverse distance (reads sXF of current tile) ----
        if (tid < MROWS) {
            const int p = tid >> 3, i = tid & 7;
            if (i >= 1 && i < 7) {
                float d2 = 0.f;
#pragma unroll
                for (int j = 0; j < 7; j++) {
                    float d = sXF[(p * 8) * 8 + j] - sXF[tid * 8 + j];
                    d2 += d * d;
                }
                sInv[p * 6 + (i - 1)] = rsqrtf(d2);
            }
        }

        // ---- R = relu(x@W1 + b1) -> fp16 swizzled A ----
        {
            const int r = tid >> 3, kg = tid & 7, k0 = kg * 32;
            ull xp[7];
#pragma unroll
            for (int j = 0; j < 7; j++) { float x = sXF[r * 8 + j]; xp[j] = pk2(x, x); }
            ull acc[16];
#pragma unroll
            for (int m = 0; m < 16; m++) acc[m] = *(const ull*)(sB1 + k0 + 2 * m);
#pragma unroll
            for (int j = 0; j < 7; j++) {
                const ull* wp = (const ull*)(sW1 + j * 256 + k0);
#pragma unroll
                for (int m = 0; m < 16; m++) fma2(acc[m], xp[j], wp[m]);
            }
#pragma unroll
            for (int g = 0; g < 4; g++) {
                uint32_t h[4];
#pragma unroll
                for (int q = 0; q < 4; q++) {
                    float a, b; unpk2(acc[g * 4 + q], a, b);
                    h[q] = f22u(fmaxf(a, 0.f), fmaxf(b, 0.f));
                }
                uint32_t u = (uint32_t)((kg * 4 + g) ^ (r & 7));
                *(uint4*)(smem + M_A + r * 512 + (u << 4)) = make_uint4(h[0], h[1], h[2], h[3]);
            }
        }
        __syncthreads();

        // ---- MMA mainloop: Z = A @ B^T (128x256x256) ----
        float acc[2][4][4];
#pragma unroll
        for (int mt = 0; mt < 2; mt++)
#pragma unroll
            for (int nt = 0; nt < 4; nt++)
#pragma unroll
                for (int q = 0; q < 4; q++) acc[mt][nt][q] = 0.f;

#pragma unroll
        for (int ks = 0; ks < 16; ks++) {
            uint32_t a0[4], a1[4];
            ldsm_x4(a0, aT0 + (((uint32_t)ks * 32 + s16) ^ aC0));
            ldsm_x4(a1, aT1 + (((uint32_t)ks * 32 + s16) ^ aC1));
#pragma unroll
            for (int nt = 0; nt < 4; nt++) {
                uint32_t b0, b1;
                ldsm_x2(b0, b1, bT[nt] + (((uint32_t)ks * 32 + bs16) ^ bC[nt]));
                mma_16816(acc[0][nt], a0, b0, b1);
                mma_16816(acc[1][nt], a1, b0, b1);
            }
        }

        // ---- epilogue: relu(Z+ep).A2 partials ----
        const uint32_t* sEPc = (const uint32_t*)(smem + M_EP + ping * 8192);
#pragma unroll
        for (int mt = 0; mt < 2; mt++)
#pragma unroll
            for (int x = 0; x < 2; x++) {
                int row = wm * 32 + mt * 16 + x * 8 + l4;
                int p = row >> 3;
                float s = 0.f;
#pragma unroll
                for (int nt = 0; nt < 4; nt++) {
                    int col = wn * 32 + nt * 8 + l2;
                    __half2 ev = *(__half2*)&sEPc[p * 128 + (col >> 1)];
                    float z0 = acc[mt][nt][2 * x]     + __low2float(ev);
                    float z1 = acc[mt][nt][2 * x + 1] + __high2float(ev);
                    s = fmaf(fmaxf(z0, 0.f), sA2[col], s);
                    s = fmaf(fmaxf(z1, 0.f), sA2[col + 1], s);
                }
                s += __shfl_xor_sync(0xffffffffu, s, 1);
                s += __shfl_xor_sync(0xffffffffu, s, 2);
                if ((lane & 3) == 0) sRow[row * 8 + wn] = s;
            }
        __syncthreads();

        // ---- finalize output ----
        if (tid < PTILE) {
            float num = 0.f, den = 0.f, sc = 0.f;
#pragma unroll
            for (int i = 0; i < 7; i++) {
                float s = Ab2v;
                const float* rp = &sRow[(tid * 8 + i) * 8];
#pragma unroll
                for (int w = 0; w < 8; w++) s += rp[w];
                if (i == 0) sc = s;
                else {
                    float iv = sInv[tid * 6 + (i - 1)];
                    num = fmaf(s, iv, num);
                    den += iv;
                }
            }
            out[(n0 + tid) * NV + v] = 0.5f * sc + 0.5f * num / den;
        }

        // ---- store next tile features ----
        if (tid < MROWS && nv_ok) {
#pragma unroll
            for (int j = 0; j < 7; j++) sXF[tid * 8 + j] = f[j];
            sXF[tid * 8 + 7] = 0.f;
        }
        cp_wait0();
        __syncthreads();
        ping ^= 1;
    }
}

// ---------------- launch ----------------
extern "C" void kernel_launch(void* const* d_in, const int* in_sizes, int n_in,
                              void* d_out, int out_size) {
    const float* centers  = (const float*)d_in[0];
    const float* encG     = (const float*)d_in[1];
    const float* encN     = (const float*)d_in[2];
    const float* nbrs     = (const float*)d_in[3];
    const float* norms    = (const float*)d_in[4];
    const float* nbrnorms = (const float*)d_in[5];
    const float* areas    = (const float*)d_in[6];
    const float* nbrareas = (const float*)d_in[7];
    const float* W1  = (const float*)d_in[10];
    const float* b1  = (const float*)d_in[11];
    const float* W2  = (const float*)d_in[12];
    const float* b2  = (const float*)d_in[13];
    const float* A1  = (const float*)d_in[14];
    const float* Ab1 = (const float*)d_in[15];
    const float* A2  = (const float*)d_in[16];
    const float* Ab2 = (const float*)d_in[17];
    float* out = (float*)d_out;

    cudaFuncSetAttribute(ep_kernel,   cudaFuncAttributeMaxDynamicSharedMemorySize, EP_SMEM);
    cudaFuncSetAttribute(main_kernel, cudaFuncAttributeMaxDynamicSharedMemorySize, MAIN_SMEM);

    precompute_Mt<<<dim3(256, NV), 256>>>(W2, A1);
    precompute_C<<<NV, 256>>>(b2, A1, Ab1);
    precompute_Ang<<<NV * 192, 256>>>(A1);
    ep_kernel<<<dim3(GRIDX, NV), 1024, EP_SMEM>>>(encN, encG);
    main_kernel<<<dim3(GRIDX, NV), 1024, MAIN_SMEM>>>(
        centers, nbrs, norms, nbrnorms, areas, nbrareas,
        W1, b1, A2, Ab2, out);
}

// round 8
// speedup vs baseline: 1.0042x; 1.0042x over previous
#include <cuda_runtime.h>
#include <cuda_fp16.h>
#include <math.h>
#include <stdint.h>

#define NPTS   30000
#define NV     4
#define SNB    6
#define PTILE  16
#define MROWS  128
#define TILES_MAIN 1875
#define GRIDX  37
#define EP_ROWS 128
#define EP_TILES 235

typedef unsigned long long ull;

// ---------------- device scratch (allocation-free) ----------------
__device__ __align__(16) unsigned char g_Mt[NV * 131072];   // M^T fp16, swizzled [n][k] 512B rows
__device__ __align__(16) unsigned char g_Ang[NV * 98304];   // A1ng^T fp16, swizzled [h][i] 384B rows
__device__ float    g_C[NV * 256];
__device__ uint32_t g_ep[NV * NPTS * 128];                  // enc_pre half2 pairs

// ---------------- helpers ----------------
__device__ __forceinline__ uint32_t smem_u32(const void* p) {
    uint32_t a;
    asm("{ .reg .u64 t; cvta.to.shared.u64 t, %1; cvt.u32.u64 %0, t; }" : "=r"(a) : "l"(p));
    return a;
}
__device__ __forceinline__ void ldsm_x4(uint32_t r[4], uint32_t addr) {
    asm volatile("ldmatrix.sync.aligned.m8n8.x4.shared.b16 {%0,%1,%2,%3}, [%4];"
                 : "=r"(r[0]), "=r"(r[1]), "=r"(r[2]), "=r"(r[3]) : "r"(addr));
}
__device__ __forceinline__ void ldsm_x2(uint32_t& r0, uint32_t& r1, uint32_t addr) {
    asm volatile("ldmatrix.sync.aligned.m8n8.x2.shared.b16 {%0,%1}, [%2];"
                 : "=r"(r0), "=r"(r1) : "r"(addr));
}
__device__ __forceinline__ void mma_16816(float c[4], const uint32_t a[4],
                                          uint32_t b0, uint32_t b1) {
    asm volatile("mma.sync.aligned.m16n8k16.row.col.f32.f16.f16.f32 "
                 "{%0,%1,%2,%3}, {%4,%5,%6,%7}, {%8,%9}, {%0,%1,%2,%3};"
                 : "+f"(c[0]), "+f"(c[1]), "+f"(c[2]), "+f"(c[3])
                 : "r"(a[0]), "r"(a[1]), "r"(a[2]), "r"(a[3]), "r"(b0), "r"(b1));
}
__device__ __forceinline__ ull pk2(float x, float y) {
    ull r; asm("mov.b64 %0, {%1, %2};" : "=l"(r) : "f"(x), "f"(y)); return r;
}
__device__ __forceinline__ void unpk2(ull p, float& x, float& y) {
    asm("mov.b64 {%0, %1}, %2;" : "=f"(x), "=f"(y) : "l"(p));
}
__device__ __forceinline__ void fma2(ull& d, ull a, ull b) {
    asm("fma.rn.f32x2 %0, %1, %2, %0;" : "+l"(d) : "l"(a), "l"(b));
}
__device__ __forceinline__ uint32_t f22u(float a, float b) {
    __half2 h = __floats2half2_rn(a, b);
    return *reinterpret_cast<uint32_t*>(&h);
}
__device__ __forceinline__ void cp16(uint32_t dst, const void* src) {
    asm volatile("cp.async.cg.shared.global [%0], [%1], 16;" :: "r"(dst), "l"(src));
}
__device__ __forceinline__ void cp_commit() { asm volatile("cp.async.commit_group;" ::: "memory"); }
__device__ __forceinline__ void cp_wait0()  { asm volatile("cp.async.wait_group 0;" ::: "memory"); }

// swizzled byte offsets: 16B-unit index XOR (row&7)
__device__ __forceinline__ uint32_t swz512(int r, int k) {   // 256 halves per row
    return (uint32_t)(r * 512 + ((((k >> 3) ^ (r & 7))) << 4) + (k & 7) * 2);
}
__device__ __forceinline__ uint32_t swz384(int r, int k) {   // 192 halves per row
    return (uint32_t)(r * 384 + ((((k >> 3) ^ (r & 7))) << 4) + (k & 7) * 2);
}

// ---------------- precompute kernels ----------------
__global__ void precompute_Mt(const float* __restrict__ W2, const float* __restrict__ A1) {
    int v = blockIdx.y, k = blockIdx.x, n = threadIdx.x;   // M[k][n]
    __shared__ float w2row[128];
    if (threadIdx.x < 128) w2row[threadIdx.x] = W2[(v * 256 + k) * 128 + threadIdx.x];
    __syncthreads();
    const float* a1 = A1 + (v * 320) * 256 + n;
    float acc = 0.f;
#pragma unroll 8
    for (int o = 0; o < 128; o++) acc += w2row[o] * a1[o * 256];
    *(__half*)(g_Mt + v * 131072 + swz512(n, k)) = __float2half(acc);
}

__global__ void precompute_C(const float* __restrict__ b2, const float* __restrict__ A1,
                             const float* __restrict__ Ab1) {
    int v = blockIdx.x, h = threadIdx.x;
    __shared__ float b2s[128];
    if (threadIdx.x < 128) b2s[threadIdx.x] = b2[v * 128 + threadIdx.x];
    __syncthreads();
    float acc = Ab1[v * 256 + h];
#pragma unroll 8
    for (int o = 0; o < 128; o++) acc += b2s[o] * A1[(v * 320 + o) * 256 + h];
    g_C[v * 256 + h] = acc;
}

__global__ void precompute_Ang(const float* __restrict__ A1) {
    int b = blockIdx.x;           // NV*192
    int v = b / 192, i = b % 192, h = threadIdx.x;
    *(__half*)(g_Ang + v * 98304 + swz384(h, i)) =
        __float2half(A1[(v * 320 + 128 + i) * 256 + h]);
}

// ---------------- ep prepass ----------------
#define E_B 0
#define E_A 98304
#define E_C 147456
#define EP_SMEM 148480

__global__ void __launch_bounds__(1024, 1)
ep_kernel(const float* __restrict__ encN, const float* __restrict__ encG) {
    extern __shared__ unsigned char smem[];
    const uint32_t sb = smem_u32(smem);
    const int tid = threadIdx.x, wid = tid >> 5, lane = tid & 31;
    const int v = blockIdx.y;
    const int wm = wid & 3, wn = wid >> 2;       // 4 m-warps x 8 n-warps, tile 32x32

    { // B copy (swizzle-preserving)
        const float4* src = (const float4*)(g_Ang + v * 98304);
        float4* dst = (float4*)(smem + E_B);
        for (int i = tid; i < 6144; i += 1024) dst[i] = src[i];
    }
    float* sC = (float*)(smem + E_C);
    if (tid < 256) sC[tid] = g_C[v * 256 + tid];
    __syncthreads();

    const int arow0 = wm * 32 + (lane & 15), arow1 = arow0 + 16;
    const uint32_t aT0 = sb + E_A + arow0 * 384, aC0 = (uint32_t)(arow0 & 7) << 4;
    const uint32_t aT1 = sb + E_A + arow1 * 384, aC1 = (uint32_t)(arow1 & 7) << 4;
    const uint32_t s16 = (uint32_t)(lane >> 4) * 16;
    uint32_t bT[4], bC[4];
#pragma unroll
    for (int nt = 0; nt < 4; nt++) {
        int brow = wn * 32 + nt * 8 + (lane & 7);
        bT[nt] = sb + E_B + brow * 384;
        bC[nt] = (uint32_t)(brow & 7) << 4;
    }
    const uint32_t bs16 = (uint32_t)((lane >> 3) & 1) * 16;
    const int l4 = lane >> 2, l2 = (lane & 3) * 2;

    for (int t = blockIdx.x; t < EP_TILES; t += GRIDX) {
        const int n0 = t * EP_ROWS;
        for (int i = tid; i < 12288; i += 1024) {
            int r = i / 96, kk = (i % 96) * 2, n = n0 + r;
            float e0 = 0.f, e1 = 0.f;
            if (n < NPTS) {
                if (kk < 128) { e0 = encN[n * 128 + kk];      e1 = encN[n * 128 + kk + 1]; }
                else          { e0 = encG[n * 64 + kk - 128]; e1 = encG[n * 64 + kk - 127]; }
            }
            *(uint32_t*)(smem + E_A + swz384(r, kk)) = f22u(e0, e1);
        }
        __syncthreads();

        float acc[2][4][4];
#pragma unroll
        for (int mt = 0; mt < 2; mt++)
#pragma unroll
            for (int nt = 0; nt < 4; nt++)
#pragma unroll
                for (int q = 0; q < 4; q++) acc[mt][nt][q] = 0.f;

#pragma unroll
        for (int ks = 0; ks < 12; ks++) {
            uint32_t a0[4], a1[4];
            ldsm_x4(a0, aT0 + (((uint32_t)ks * 32 + s16) ^ aC0));
            ldsm_x4(a1, aT1 + (((uint32_t)ks * 32 + s16) ^ aC1));
#pragma unroll
            for (int nt = 0; nt < 4; nt++) {
                uint32_t b0, b1;
                ldsm_x2(b0, b1, bT[nt] + (((uint32_t)ks * 32 + bs16) ^ bC[nt]));
                mma_16816(acc[0][nt], a0, b0, b1);
                mma_16816(acc[1][nt], a1, b0, b1);
            }
        }

#pragma unroll
        for (int mt = 0; mt < 2; mt++)
#pragma unroll
            for (int x = 0; x < 2; x++) {
                int row = wm * 32 + mt * 16 + x * 8 + l4;
                int n = n0 + row;
                if (n < NPTS) {
                    uint32_t* dst = &g_ep[(v * NPTS + n) * 128];
#pragma unroll
                    for (int nt = 0; nt < 4; nt++) {
                        int col = wn * 32 + nt * 8 + l2;
                        dst[col >> 1] = f22u(acc[mt][nt][2 * x] + sC[col],
                                             acc[mt][nt][2 * x + 1] + sC[col + 1]);
                    }
                }
            }
        __syncthreads();
    }
}

// ---------------- main fused kernel ----------------
#define M_B   0
#define M_A   131072
#define M_EP  196608          // 2 x 8192
#define M_W1  212992
#define M_B1  220160
#define M_A2  221184
#define M_XF  222208
#define M_INV 226304
#define M_ROW 226816
#define MAIN_SMEM 230912

__global__ void __launch_bounds__(1024, 1)
main_kernel(const float* __restrict__ centers,  const float* __restrict__ nbrs,
            const float* __restrict__ norms,    const float* __restrict__ nbrnorms,
            const float* __restrict__ areas,    const float* __restrict__ nbrareas,
            const float* __restrict__ W1,       const float* __restrict__ b1,
            const float* __restrict__ A2,       const float* __restrict__ Ab2,
            float* __restrict__ out) {
    extern __shared__ unsigned char smem[];
    const uint32_t sb = smem_u32(smem);
    const int tid = threadIdx.x, wid = tid >> 5, lane = tid & 31;
    const int v = blockIdx.y;
    const int wm = wid & 3, wn = wid >> 2;       // 4 m-warps x 8 n-warps

    float* sW1  = (float*)(smem + M_W1);
    float* sB1  = (float*)(smem + M_B1);
    float* sA2  = (float*)(smem + M_A2);
    float* sXF  = (float*)(smem + M_XF);
    float* sInv = (float*)(smem + M_INV);
    float* sRow = (float*)(smem + M_ROW);

    { // resident B = M^T (128 KB, swizzled)
        const float4* src = (const float4*)(g_Mt + v * 131072);
        float4* dst = (float4*)(smem + M_B);
        for (int i = tid; i < 8192; i += 1024) dst[i] = src[i];
    }
    if (tid < 256) { sA2[tid] = A2[v * 256 + tid]; sB1[tid] = b1[v * 256 + tid]; }
    for (int i = tid; i < 7 * 256; i += 1024) sW1[i] = W1[v * 7 * 256 + i];
    const float Ab2v = Ab2[v];

    // ---- prologue: stage xf + ep for first tile ----
    const int t0 = blockIdx.x;
    if (tid < MROWS) {
        const int p = tid >> 3, i = tid & 7, n = t0 * PTILE + p;
        float f[7];
        if (i == 0) {
            f[0] = centers[n * 3 + 0]; f[1] = centers[n * 3 + 1]; f[2] = centers[n * 3 + 2];
            f[3] = norms[n * 3 + 0];   f[4] = norms[n * 3 + 1];   f[5] = norms[n * 3 + 2];
            f[6] = __logf(areas[n]) * 0.1f;
        } else if (i < 7) {
            int s = i - 1, base = (n * SNB + s) * 3;
            f[0] = nbrs[base + 0] + 1e-6f;     f[1] = nbrs[base + 1] + 1e-6f;     f[2] = nbrs[base + 2] + 1e-6f;
            f[3] = nbrnorms[base + 0] + 1e-6f; f[4] = nbrnorms[base + 1] + 1e-6f; f[5] = nbrnorms[base + 2] + 1e-6f;
            f[6] = __logf(nbrareas[n * SNB + s]) * 0.1f + 1e-6f;
        } else {
#pragma unroll
            for (int j = 0; j < 7; j++) f[j] = 0.f;
        }
#pragma unroll
        for (int j = 0; j < 7; j++) sXF[tid * 8 + j] = f[j];
        sXF[tid * 8 + 7] = 0.f;
    }
    if (tid < 512)
        cp16(sb + M_EP + tid * 16,
             (const unsigned char*)g_ep + (size_t)(v * NPTS + t0 * PTILE) * 512 + tid * 16);
    cp_commit();
    cp_wait0();
    __syncthreads();

    // lane-constant LDSM address terms
    const int arow0 = wm * 32 + (lane & 15), arow1 = arow0 + 16;
    const uint32_t aT0 = sb + M_A + arow0 * 512, aC0 = (uint32_t)(arow0 & 7) << 4;
    const uint32_t aT1 = sb + M_A + arow1 * 512, aC1 = (uint32_t)(arow1 & 7) << 4;
    const uint32_t s16 = (uint32_t)(lane >> 4) * 16;
    uint32_t bT[4], bC[4];
#pragma unroll
    for (int nt = 0; nt < 4; nt++) {
        int brow = wn * 32 + nt * 8 + (lane & 7);
        bT[nt] = sb + M_B + brow * 512;
        bC[nt] = (uint32_t)(brow & 7) << 4;
    }
    const uint32_t bs16 = (uint32_t)((lane >> 3) & 1) * 16;
    const int l4 = lane >> 2, l2 = (lane & 3) * 2;

    int ping = 0;
    for (int t = t0; t < TILES_MAIN; t += GRIDX) {
        const int n0 = t * PTILE;
        const int tn = t + GRIDX;
        const bool nv_ok = (tn < TILES_MAIN);

        // ---- prefetch next tile's ep via cp.async into other buffer ----
        if (tid < 512 && nv_ok)
            cp16(sb + M_EP + (ping ^ 1) * 8192 + tid * 16,
                 (const unsigned char*)g_ep + (size_t)(v * NPTS + tn * PTILE) * 512 + tid * 16);
        cp_commit();

        // ---- inverse distance (reads sXF of current tile) ----
        if (tid < MROWS) {
            const int p = tid >> 3, i = tid & 7;
            if (i >= 1 && i < 7) {
                float d2 = 0.f;
#pragma unroll
                for (int j = 0; j < 7; j++) {
                    float d = sXF[(p * 8) * 8 + j] - sXF[tid * 8 + j];
                    d2 += d * d;
                }
                sInv[p * 6 + (i - 1)] = rsqrtf(d2);
            }
        }

        // ---- R = relu(x@W1 + b1) -> fp16 swizzled A (two 8-acc half-passes) ----
        {
            const int r = tid >> 3, kg = tid & 7;
            ull xp[7];
#pragma unroll
            for (int j = 0; j < 7; j++) { float x = sXF[r * 8 + j]; xp[j] = pk2(x, x); }
#pragma unroll
            for (int hf = 0; hf < 2; hf++) {
                const int k0 = kg * 32 + hf * 16;
                ull acc[8];
#pragma unroll
                for (int m = 0; m < 8; m++) acc[m] = *(const ull*)(sB1 + k0 + 2 * m);
#pragma unroll
                for (int j = 0; j < 7; j++) {
                    const ull* wp = (const ull*)(sW1 + j * 256 + k0);
#pragma unroll
                    for (int m = 0; m < 8; m++) fma2(acc[m], xp[j], wp[m]);
                }
#pragma unroll
                for (int g = 0; g < 2; g++) {
                    uint32_t h[4];
#pragma unroll
                    for (int q = 0; q < 4; q++) {
                        float a, b; unpk2(acc[g * 4 + q], a, b);
                        h[q] = f22u(fmaxf(a, 0.f), fmaxf(b, 0.f));
                    }
                    uint32_t u = (uint32_t)((kg * 4 + hf * 2 + g) ^ (r & 7));
                    *(uint4*)(smem + M_A + r * 512 + (u << 4)) = make_uint4(h[0], h[1], h[2], h[3]);
                }
            }
        }
        __syncthreads();

        // ---- MMA mainloop: Z = A @ B^T (128x256x256) ----
        float acc[2][4][4];
#pragma unroll
        for (int mt = 0; mt < 2; mt++)
#pragma unroll
            for (int nt = 0; nt < 4; nt++)
#pragma unroll
                for (int q = 0; q < 4; q++) acc[mt][nt][q] = 0.f;

#pragma unroll
        for (int ks = 0; ks < 16; ks++) {
            uint32_t a0[4], a1[4];
            ldsm_x4(a0, aT0 + (((uint32_t)ks * 32 + s16) ^ aC0));
            ldsm_x4(a1, aT1 + (((uint32_t)ks * 32 + s16) ^ aC1));
#pragma unroll
            for (int nt = 0; nt < 4; nt++) {
                uint32_t b0, b1;
                ldsm_x2(b0, b1, bT[nt] + (((uint32_t)ks * 32 + bs16) ^ bC[nt]));
                mma_16816(acc[0][nt], a0, b0, b1);
                mma_16816(acc[1][nt], a1, b0, b1);
            }
        }

        // ---- epilogue: relu(Z+ep).A2 partials ----
        const uint32_t* sEPc = (const uint32_t*)(smem + M_EP + ping * 8192);
#pragma unroll
        for (int mt = 0; mt < 2; mt++)
#pragma unroll
            for (int x = 0; x < 2; x++) {
                int row = wm * 32 + mt * 16 + x * 8 + l4;
                int p = row >> 3;
                float s = 0.f;
#pragma unroll
                for (int nt = 0; nt < 4; nt++) {
                    int col = wn * 32 + nt * 8 + l2;
                    __half2 ev = *(__half2*)&sEPc[p * 128 + (col >> 1)];
                    float z0 = acc[mt][nt][2 * x]     + __low2float(ev);
                    float z1 = acc[mt][nt][2 * x + 1] + __high2float(ev);
                    s = fmaf(fmaxf(z0, 0.f), sA2[col], s);
                    s = fmaf(fmaxf(z1, 0.f), sA2[col + 1], s);
                }
                s += __shfl_xor_sync(0xffffffffu, s, 1);
                s += __shfl_xor_sync(0xffffffffu, s, 2);
                if ((lane & 3) == 0) sRow[row * 8 + wn] = s;
            }
        __syncthreads();

        // ---- finalize output ----
        if (tid < PTILE) {
            float num = 0.f, den = 0.f, sc = 0.f;
#pragma unroll
            for (int i = 0; i < 7; i++) {
                float s = Ab2v;
                const float* rp = &sRow[(tid * 8 + i) * 8];
#pragma unroll
                for (int w = 0; w < 8; w++) s += rp[w];
                if (i == 0) sc = s;
                else {
                    float iv = sInv[tid * 6 + (i - 1)];
                    num = fmaf(s, iv, num);
                    den += iv;
                }
            }
            out[(n0 + tid) * NV + v] = 0.5f * sc + 0.5f * num / den;
        }

        // ---- restage next tile features (no cross-mainloop register pressure) ----
        if (tid < MROWS && nv_ok) {
            const int p = tid >> 3, i = tid & 7, n = tn * PTILE + p;
            float f[7];
            if (i == 0) {
                f[0] = centers[n * 3 + 0]; f[1] = centers[n * 3 + 1]; f[2] = centers[n * 3 + 2];
                f[3] = norms[n * 3 + 0];   f[4] = norms[n * 3 + 1];   f[5] = norms[n * 3 + 2];
                f[6] = __logf(areas[n]) * 0.1f;
            } else if (i < 7) {
                int s = i - 1, base = (n * SNB + s) * 3;
                f[0] = nbrs[base + 0] + 1e-6f;     f[1] = nbrs[base + 1] + 1e-6f;     f[2] = nbrs[base + 2] + 1e-6f;
                f[3] = nbrnorms[base + 0] + 1e-6f; f[4] = nbrnorms[base + 1] + 1e-6f; f[5] = nbrnorms[base + 2] + 1e-6f;
                f[6] = __logf(nbrareas[n * SNB + s]) * 0.1f + 1e-6f;
            } else {
#pragma unroll
                for (int j = 0; j < 7; j++) f[j] = 0.f;
            }
#pragma unroll
            for (int j = 0; j < 7; j++) sXF[tid * 8 + j] = f[j];
            sXF[tid * 8 + 7] = 0.f;
        }
        cp_wait0();
        __syncthreads();
        ping ^= 1;
    }
}

// ---------------- launch ----------------
extern "C" void kernel_launch(void* const* d_in, const int* in_sizes, int n_in,
                              void* d_out, int out_size) {
    const float* centers  = (const float*)d_in[0];
    const float* encG     = (const float*)d_in[1];
    const float* encN     = (const float*)d_in[2];
    const float* nbrs     = (const float*)d_in[3];
    const float* norms    = (const float*)d_in[4];
    const float* nbrnorms = (const float*)d_in[5];
    const float* areas    = (const float*)d_in[6];
    const float* nbrareas = (const float*)d_in[7];
    const float* W1  = (const float*)d_in[10];
    const float* b1  = (const float*)d_in[11];
    const float* W2  = (const float*)d_in[12];
    const float* b2  = (const float*)d_in[13];
    const float* A1  = (const float*)d_in[14];
    const float* Ab1 = (const float*)d_in[15];
    const float* A2  = (const float*)d_in[16];
    const float* Ab2 = (const float*)d_in[17];
    float* out = (float*)d_out;

    cudaFuncSetAttribute(ep_kernel,   cudaFuncAttributeMaxDynamicSharedMemorySize, EP_SMEM);
    cudaFuncSetAttribute(main_kernel, cudaFuncAttributeMaxDynamicSharedMemorySize, MAIN_SMEM);

    precompute_Mt<<<dim3(256, NV), 256>>>(W2, A1);
    precompute_C<<<NV, 256>>>(b2, A1, Ab1);
    precompute_Ang<<<NV * 192, 256>>>(A1);
    ep_kernel<<<dim3(GRIDX, NV), 1024, EP_SMEM>>>(encN, encG);
    main_kernel<<<dim3(GRIDX, NV), 1024, MAIN_SMEM>>>(
        centers, nbrs, norms, nbrnorms, areas, nbrareas,
        W1, b1, A2, Ab2, out);
}

// round 9
// speedup vs baseline: 1.6469x; 1.6400x over previous
#include <cuda_runtime.h>
#include <cuda_fp16.h>
#include <math.h>
#include <stdint.h>

#define NPTS   30000
#define NV     4
#define SNB    6
#define PTILE  16
#define MROWS  128
#define TILES_MAIN 1875
#define GRIDX  37
#define EP_ROWS 128
#define EP_TILES 235

typedef unsigned long long ull;

// ---------------- device scratch (allocation-free) ----------------
__device__ __align__(16) unsigned char g_Mt[NV * 131072];   // M^T fp16, swizzled [n][k] 512B rows
__device__ __align__(16) unsigned char g_Ang[NV * 98304];   // A1ng^T fp16, swizzled [h][i] 384B rows
__device__ float    g_C[NV * 256];
__device__ uint32_t g_ep[NV * NPTS * 128];                  // enc_pre half2 pairs

// ---------------- helpers ----------------
__device__ __forceinline__ uint32_t smem_u32(const void* p) {
    uint32_t a;
    asm("{ .reg .u64 t; cvta.to.shared.u64 t, %1; cvt.u32.u64 %0, t; }" : "=r"(a) : "l"(p));
    return a;
}
__device__ __forceinline__ void ldsm_x4(uint32_t r[4], uint32_t addr) {
    asm volatile("ldmatrix.sync.aligned.m8n8.x4.shared.b16 {%0,%1,%2,%3}, [%4];"
                 : "=r"(r[0]), "=r"(r[1]), "=r"(r[2]), "=r"(r[3]) : "r"(addr));
}
__device__ __forceinline__ void ldsm_x2(uint32_t& r0, uint32_t& r1, uint32_t addr) {
    asm volatile("ldmatrix.sync.aligned.m8n8.x2.shared.b16 {%0,%1}, [%2];"
                 : "=r"(r0), "=r"(r1) : "r"(addr));
}
__device__ __forceinline__ void mma_16816(float c[4], const uint32_t a[4],
                                          uint32_t b0, uint32_t b1) {
    asm volatile("mma.sync.aligned.m16n8k16.row.col.f32.f16.f16.f32 "
                 "{%0,%1,%2,%3}, {%4,%5,%6,%7}, {%8,%9}, {%0,%1,%2,%3};"
                 : "+f"(c[0]), "+f"(c[1]), "+f"(c[2]), "+f"(c[3])
                 : "r"(a[0]), "r"(a[1]), "r"(a[2]), "r"(a[3]), "r"(b0), "r"(b1));
}
__device__ __forceinline__ ull pk2(float x, float y) {
    ull r; asm("mov.b64 %0, {%1, %2};" : "=l"(r) : "f"(x), "f"(y)); return r;
}
__device__ __forceinline__ void unpk2(ull p, float& x, float& y) {
    asm("mov.b64 {%0, %1}, %2;" : "=f"(x), "=f"(y) : "l"(p));
}
__device__ __forceinline__ void fma2(ull& d, ull a, ull b) {
    asm("fma.rn.f32x2 %0, %1, %2, %0;" : "+l"(d) : "l"(a), "l"(b));
}
__device__ __forceinline__ uint32_t f22u(float a, float b) {
    __half2 h = __floats2half2_rn(a, b);
    return *reinterpret_cast<uint32_t*>(&h);
}
__device__ __forceinline__ void cp16(uint32_t dst, const void* src) {
    asm volatile("cp.async.cg.shared.global [%0], [%1], 16;" :: "r"(dst), "l"(src));
}
__device__ __forceinline__ void cp_commit() { asm volatile("cp.async.commit_group;" ::: "memory"); }
__device__ __forceinline__ void cp_wait0()  { asm volatile("cp.async.wait_group 0;" ::: "memory"); }

// swizzled byte offsets: 16B-unit index XOR (row&7)
__device__ __forceinline__ uint32_t swz512(int r, int k) {   // 256 halves per row
    return (uint32_t)(r * 512 + ((((k >> 3) ^ (r & 7))) << 4) + (k & 7) * 2);
}
__device__ __forceinline__ uint32_t swz384(int r, int k) {   // 192 halves per row
    return (uint32_t)(r * 384 + ((((k >> 3) ^ (r & 7))) << 4) + (k & 7) * 2);
}

// ---------------- precompute kernels ----------------
__global__ void precompute_Mt(const float* __restrict__ W2, const float* __restrict__ A1) {
    int v = blockIdx.y, k = blockIdx.x, n = threadIdx.x;   // M[k][n]
    __shared__ float w2row[128];
    if (threadIdx.x < 128) w2row[threadIdx.x] = W2[(v * 256 + k) * 128 + threadIdx.x];
    __syncthreads();
    const float* a1 = A1 + (v * 320) * 256 + n;
    float acc = 0.f;
#pragma unroll 8
    for (int o = 0; o < 128; o++) acc += w2row[o] * a1[o * 256];
    *(__half*)(g_Mt + v * 131072 + swz512(n, k)) = __float2half(acc);
}

__global__ void precompute_C(const float* __restrict__ b2, const float* __restrict__ A1,
                             const float* __restrict__ Ab1) {
    int v = blockIdx.x, h = threadIdx.x;
    __shared__ float b2s[128];
    if (threadIdx.x < 128) b2s[threadIdx.x] = b2[v * 128 + threadIdx.x];
    __syncthreads();
    float acc = Ab1[v * 256 + h];
#pragma unroll 8
    for (int o = 0; o < 128; o++) acc += b2s[o] * A1[(v * 320 + o) * 256 + h];
    g_C[v * 256 + h] = acc;
}

__global__ void precompute_Ang(const float* __restrict__ A1) {
    int b = blockIdx.x;           // NV*192
    int v = b / 192, i = b % 192, h = threadIdx.x;
    *(__half*)(g_Ang + v * 98304 + swz384(h, i)) =
        __float2half(A1[(v * 320 + 128 + i) * 256 + h]);
}

// ---------------- ep prepass (unchanged from R8: 100us, regs=64, no spills) ----------------
#define E_B 0
#define E_A 98304
#define E_C 147456
#define EP_SMEM 148480

__global__ void __launch_bounds__(1024, 1)
ep_kernel(const float* __restrict__ encN, const float* __restrict__ encG) {
    extern __shared__ unsigned char smem[];
    const uint32_t sb = smem_u32(smem);
    const int tid = threadIdx.x, wid = tid >> 5, lane = tid & 31;
    const int v = blockIdx.y;
    const int wm = wid & 3, wn = wid >> 2;

    {
        const float4* src = (const float4*)(g_Ang + v * 98304);
        float4* dst = (float4*)(smem + E_B);
        for (int i = tid; i < 6144; i += 1024) dst[i] = src[i];
    }
    float* sC = (float*)(smem + E_C);
    if (tid < 256) sC[tid] = g_C[v * 256 + tid];
    __syncthreads();

    const int arow0 = wm * 32 + (lane & 15), arow1 = arow0 + 16;
    const uint32_t aT0 = sb + E_A + arow0 * 384, aC0 = (uint32_t)(arow0 & 7) << 4;
    const uint32_t aT1 = sb + E_A + arow1 * 384, aC1 = (uint32_t)(arow1 & 7) << 4;
    const uint32_t s16 = (uint32_t)(lane >> 4) * 16;
    uint32_t bT[4], bC[4];
#pragma unroll
    for (int nt = 0; nt < 4; nt++) {
        int brow = wn * 32 + nt * 8 + (lane & 7);
        bT[nt] = sb + E_B + brow * 384;
        bC[nt] = (uint32_t)(brow & 7) << 4;
    }
    const uint32_t bs16 = (uint32_t)((lane >> 3) & 1) * 16;
    const int l4 = lane >> 2, l2 = (lane & 3) * 2;

    for (int t = blockIdx.x; t < EP_TILES; t += GRIDX) {
        const int n0 = t * EP_ROWS;
        for (int i = tid; i < 12288; i += 1024) {
            int r = i / 96, kk = (i % 96) * 2, n = n0 + r;
            float e0 = 0.f, e1 = 0.f;
            if (n < NPTS) {
                if (kk < 128) { e0 = encN[n * 128 + kk];      e1 = encN[n * 128 + kk + 1]; }
                else          { e0 = encG[n * 64 + kk - 128]; e1 = encG[n * 64 + kk - 127]; }
            }
            *(uint32_t*)(smem + E_A + swz384(r, kk)) = f22u(e0, e1);
        }
        __syncthreads();

        float acc[2][4][4];
#pragma unroll
        for (int mt = 0; mt < 2; mt++)
#pragma unroll
            for (int nt = 0; nt < 4; nt++)
#pragma unroll
                for (int q = 0; q < 4; q++) acc[mt][nt][q] = 0.f;

#pragma unroll
        for (int ks = 0; ks < 12; ks++) {
            uint32_t a0[4], a1[4];
            ldsm_x4(a0, aT0 + (((uint32_t)ks * 32 + s16) ^ aC0));
            ldsm_x4(a1, aT1 + (((uint32_t)ks * 32 + s16) ^ aC1));
#pragma unroll
            for (int nt = 0; nt < 4; nt++) {
                uint32_t b0, b1;
                ldsm_x2(b0, b1, bT[nt] + (((uint32_t)ks * 32 + bs16) ^ bC[nt]));
                mma_16816(acc[0][nt], a0, b0, b1);
                mma_16816(acc[1][nt], a1, b0, b1);
            }
        }

#pragma unroll
        for (int mt = 0; mt < 2; mt++)
#pragma unroll
            for (int x = 0; x < 2; x++) {
                int row = wm * 32 + mt * 16 + x * 8 + l4;
                int n = n0 + row;
                if (n < NPTS) {
                    uint32_t* dst = &g_ep[(v * NPTS + n) * 128];
#pragma unroll
                    for (int nt = 0; nt < 4; nt++) {
                        int col = wn * 32 + nt * 8 + l2;
                        dst[col >> 1] = f22u(acc[mt][nt][2 * x] + sC[col],
                                             acc[mt][nt][2 * x + 1] + sC[col + 1]);
                    }
                }
            }
        __syncthreads();
    }
}

// ---------------- main fused kernel: 512 threads, 128 regs, pipelined ----------------
#define M_B   0
#define M_A   131072
#define M_EP  196608          // 2 x 8192
#define M_W1  212992
#define M_B1  220160
#define M_A2  221184
#define M_XF  222208
#define M_INV 226304
#define M_ROW 226816          // 128 x 4 floats
#define MAIN_SMEM 229888

__global__ void __launch_bounds__(512, 1)
main_kernel(const float* __restrict__ centers,  const float* __restrict__ nbrs,
            const float* __restrict__ norms,    const float* __restrict__ nbrnorms,
            const float* __restrict__ areas,    const float* __restrict__ nbrareas,
            const float* __restrict__ W1,       const float* __restrict__ b1,
            const float* __restrict__ A2,       const float* __restrict__ Ab2,
            float* __restrict__ out) {
    extern __shared__ unsigned char smem[];
    const uint32_t sb = smem_u32(smem);
    const int tid = threadIdx.x, wid = tid >> 5, lane = tid & 31;
    const int v = blockIdx.y;
    const int wm = wid & 3, wn = wid >> 2;       // 4 m-warps x 4 n-warps, warp tile 32x64

    float* sW1  = (float*)(smem + M_W1);
    float* sB1  = (float*)(smem + M_B1);
    float* sA2  = (float*)(smem + M_A2);
    float* sXF  = (float*)(smem + M_XF);
    float* sInv = (float*)(smem + M_INV);
    float* sRow = (float*)(smem + M_ROW);

    { // resident B = M^T (128 KB, swizzled)
        const float4* src = (const float4*)(g_Mt + v * 131072);
        float4* dst = (float4*)(smem + M_B);
        for (int i = tid; i < 8192; i += 512) dst[i] = src[i];
    }
    if (tid < 256) { sA2[tid] = A2[v * 256 + tid]; sB1[tid] = b1[v * 256 + tid]; }
    for (int i = tid; i < 7 * 256; i += 512) sW1[i] = W1[v * 7 * 256 + i];
    const float Ab2v = Ab2[v];

    // ---- prologue: stage xf + ep for first tile ----
    const int t0 = blockIdx.x;
    if (tid < MROWS) {
        const int p = tid >> 3, i = tid & 7, n = t0 * PTILE + p;
        float f[7];
        if (i == 0) {
            f[0] = centers[n * 3 + 0]; f[1] = centers[n * 3 + 1]; f[2] = centers[n * 3 + 2];
            f[3] = norms[n * 3 + 0];   f[4] = norms[n * 3 + 1];   f[5] = norms[n * 3 + 2];
            f[6] = __logf(areas[n]) * 0.1f;
        } else if (i < 7) {
            int s = i - 1, base = (n * SNB + s) * 3;
            f[0] = nbrs[base + 0] + 1e-6f;     f[1] = nbrs[base + 1] + 1e-6f;     f[2] = nbrs[base + 2] + 1e-6f;
            f[3] = nbrnorms[base + 0] + 1e-6f; f[4] = nbrnorms[base + 1] + 1e-6f; f[5] = nbrnorms[base + 2] + 1e-6f;
            f[6] = __logf(nbrareas[n * SNB + s]) * 0.1f + 1e-6f;
        } else {
#pragma unroll
            for (int j = 0; j < 7; j++) f[j] = 0.f;
        }
#pragma unroll
        for (int j = 0; j < 7; j++) sXF[tid * 8 + j] = f[j];
        sXF[tid * 8 + 7] = 0.f;
    }
    cp16(sb + M_EP + tid * 16,
         (const unsigned char*)g_ep + (size_t)(v * NPTS + t0 * PTILE) * 512 + tid * 16);
    cp_commit();
    cp_wait0();
    __syncthreads();

    // lane-constant LDSM address terms (arow&7 == brow&7 == lane&7)
    const int arow = wm * 32 + (lane & 15);
    const uint32_t aT0 = sb + M_A + arow * 512;
    const uint32_t aT1 = aT0 + 16 * 512;
    const uint32_t xc  = (uint32_t)(lane & 7) << 4;
    const uint32_t s16a = (uint32_t)(lane >> 4) * 16;
    const uint32_t s16b = (uint32_t)((lane >> 3) & 1) * 16;
    const uint32_t bT0 = sb + M_B + (wn * 64 + (lane & 7)) * 512;
    const int l4 = lane >> 2, l2 = (lane & 3) * 2;

    int ping = 0;
    for (int t = t0; t < TILES_MAIN; t += GRIDX) {
        const int n0 = t * PTILE;
        const int tn = t + GRIDX;
        const bool nv_ok = (tn < TILES_MAIN);

        // ---- prefetch next tile's ep ----
        if (nv_ok)
            cp16(sb + M_EP + (ping ^ 1) * 8192 + tid * 16,
                 (const unsigned char*)g_ep + (size_t)(v * NPTS + tn * PTILE) * 512 + tid * 16);
        cp_commit();

        // ---- inverse distance ----
        if (tid < MROWS) {
            const int p = tid >> 3, i = tid & 7;
            if (i >= 1 && i < 7) {
                float d2 = 0.f;
#pragma unroll
                for (int j = 0; j < 7; j++) {
                    float d = sXF[(p * 8) * 8 + j] - sXF[tid * 8 + j];
                    d2 += d * d;
                }
                sInv[p * 6 + (i - 1)] = rsqrtf(d2);
            }
        }

        // ---- R = relu(x@W1+b1) -> fp16 swizzled A (each thread: 1 row, 64 k) ----
        {
            const int r = tid >> 2, q = tid & 3;
            ull xp[7];
#pragma unroll
            for (int j = 0; j < 7; j++) { float x = sXF[r * 8 + j]; xp[j] = pk2(x, x); }
#pragma unroll
            for (int hf = 0; hf < 2; hf++) {
                const int k0 = q * 64 + hf * 32;
                ull acc[16];
#pragma unroll
                for (int m = 0; m < 16; m++) acc[m] = *(const ull*)(sB1 + k0 + 2 * m);
#pragma unroll
                for (int j = 0; j < 7; j++) {
                    const ull* wp = (const ull*)(sW1 + j * 256 + k0);
#pragma unroll
                    for (int m = 0; m < 16; m++) fma2(acc[m], xp[j], wp[m]);
                }
#pragma unroll
                for (int g = 0; g < 4; g++) {
                    uint32_t h[4];
#pragma unroll
                    for (int qq = 0; qq < 4; qq++) {
                        float a, b; unpk2(acc[g * 4 + qq], a, b);
                        h[qq] = f22u(fmaxf(a, 0.f), fmaxf(b, 0.f));
                    }
                    uint32_t u = (uint32_t)(((k0 >> 3) + g) ^ (r & 7));
                    *(uint4*)(smem + M_A + r * 512 + (u << 4)) = make_uint4(h[0], h[1], h[2], h[3]);
                }
            }
        }
        __syncthreads();

        // ---- MMA mainloop: Z = A @ B^T (128x256x256), pipelined ----
        float acc[2][8][4];
#pragma unroll
        for (int mt = 0; mt < 2; mt++)
#pragma unroll
            for (int nt = 0; nt < 8; nt++)
#pragma unroll
                for (int q = 0; q < 4; q++) acc[mt][nt][q] = 0.f;

        uint32_t a0[4], a1[4];
        {
            uint32_t offA = s16a ^ xc;
            ldsm_x4(a0, aT0 + offA);
            ldsm_x4(a1, aT1 + offA);
        }
#pragma unroll
        for (int ks = 0; ks < 16; ks++) {
            const uint32_t offB = ((uint32_t)ks * 32 + s16b) ^ xc;
            uint32_t b0, b1;
            ldsm_x2(b0, b1, bT0 + offB);
            uint32_t na0[4], na1[4];
            if (ks < 15) {
                uint32_t offA = ((uint32_t)(ks + 1) * 32 + s16a) ^ xc;
                ldsm_x4(na0, aT0 + offA);
                ldsm_x4(na1, aT1 + offA);
            }
#pragma unroll
            for (int nt = 0; nt < 8; nt++) {
                uint32_t c0, c1;
                if (nt < 7) ldsm_x2(c0, c1, bT0 + (uint32_t)(nt + 1) * 4096 + offB);
                mma_16816(acc[0][nt], a0, b0, b1);
                mma_16816(acc[1][nt], a1, b0, b1);
                b0 = c0; b1 = c1;
            }
            if (ks < 15) {
#pragma unroll
                for (int q = 0; q < 4; q++) { a0[q] = na0[q]; a1[q] = na1[q]; }
            }
        }

        // ---- epilogue: relu(Z+ep).A2 partials ----
        const uint32_t* sEPc = (const uint32_t*)(smem + M_EP + ping * 8192);
#pragma unroll
        for (int mt = 0; mt < 2; mt++)
#pragma unroll
            for (int x = 0; x < 2; x++) {
                int row = wm * 32 + mt * 16 + x * 8 + l4;
                int p = row >> 3;
                float s = 0.f;
#pragma unroll
                for (int nt = 0; nt < 8; nt++) {
                    int col = wn * 64 + nt * 8 + l2;
                    __half2 ev = *(__half2*)&sEPc[p * 128 + (col >> 1)];
                    float z0 = acc[mt][nt][2 * x]     + __low2float(ev);
                    float z1 = acc[mt][nt][2 * x + 1] + __high2float(ev);
                    s = fmaf(fmaxf(z0, 0.f), sA2[col], s);
                    s = fmaf(fmaxf(z1, 0.f), sA2[col + 1], s);
                }
                s += __shfl_xor_sync(0xffffffffu, s, 1);
                s += __shfl_xor_sync(0xffffffffu, s, 2);
                if ((lane & 3) == 0) sRow[row * 4 + wn] = s;
            }
        __syncthreads();

        // ---- finalize output ----
        if (tid < PTILE) {
            float num = 0.f, den = 0.f, sc = 0.f;
#pragma unroll
            for (int i = 0; i < 7; i++) {
                float s = Ab2v;
                const float* rp = &sRow[(tid * 8 + i) * 4];
#pragma unroll
                for (int w = 0; w < 4; w++) s += rp[w];
                if (i == 0) sc = s;
                else {
                    float iv = sInv[tid * 6 + (i - 1)];
                    num = fmaf(s, iv, num);
                    den += iv;
                }
            }
            out[(n0 + tid) * NV + v] = 0.5f * sc + 0.5f * num / den;
        }

        // ---- restage next tile features ----
        if (tid < MROWS && nv_ok) {
            const int p = tid >> 3, i = tid & 7, n = tn * PTILE + p;
            float f[7];
            if (i == 0) {
                f[0] = centers[n * 3 + 0]; f[1] = centers[n * 3 + 1]; f[2] = centers[n * 3 + 2];
                f[3] = norms[n * 3 + 0];   f[4] = norms[n * 3 + 1];   f[5] = norms[n * 3 + 2];
                f[6] = __logf(areas[n]) * 0.1f;
            } else if (i < 7) {
                int s = i - 1, base = (n * SNB + s) * 3;
                f[0] = nbrs[base + 0] + 1e-6f;     f[1] = nbrs[base + 1] + 1e-6f;     f[2] = nbrs[base + 2] + 1e-6f;
                f[3] = nbrnorms[base + 0] + 1e-6f; f[4] = nbrnorms[base + 1] + 1e-6f; f[5] = nbrnorms[base + 2] + 1e-6f;
                f[6] = __logf(nbrareas[n * SNB + s]) * 0.1f + 1e-6f;
            } else {
#pragma unroll
                for (int j = 0; j < 7; j++) f[j] = 0.f;
            }
#pragma unroll
            for (int j = 0; j < 7; j++) sXF[tid * 8 + j] = f[j];
            sXF[tid * 8 + 7] = 0.f;
        }
        cp_wait0();
        __syncthreads();
        ping ^= 1;
    }
}

// ---------------- launch ----------------
extern "C" void kernel_launch(void* const* d_in, const int* in_sizes, int n_in,
                              void* d_out, int out_size) {
    const float* centers  = (const float*)d_in[0];
    const float* encG     = (const float*)d_in[1];
    const float* encN     = (const float*)d_in[2];
    const float* nbrs     = (const float*)d_in[3];
    const float* norms    = (const float*)d_in[4];
    const float* nbrnorms = (const float*)d_in[5];
    const float* areas    = (const float*)d_in[6];
    const float* nbrareas = (const float*)d_in[7];
    const float* W1  = (const float*)d_in[10];
    const float* b1  = (const float*)d_in[11];
    const float* W2  = (const float*)d_in[12];
    const float* b2  = (const float*)d_in[13];
    const float* A1  = (const float*)d_in[14];
    const float* Ab1 = (const float*)d_in[15];
    const float* A2  = (const float*)d_in[16];
    const float* Ab2 = (const float*)d_in[17];
    float* out = (float*)d_out;

    cudaFuncSetAttribute(ep_kernel,   cudaFuncAttributeMaxDynamicSharedMemorySize, EP_SMEM);
    cudaFuncSetAttribute(main_kernel, cudaFuncAttributeMaxDynamicSharedMemorySize, MAIN_SMEM);

    precompute_Mt<<<dim3(256, NV), 256>>>(W2, A1);
    precompute_C<<<NV, 256>>>(b2, A1, Ab1);
    precompute_Ang<<<NV * 192, 256>>>(A1);
    ep_kernel<<<dim3(GRIDX, NV), 1024, EP_SMEM>>>(encN, encG);
    main_kernel<<<dim3(GRIDX, NV), 512, MAIN_SMEM>>>(
        centers, nbrs, norms, nbrnorms, areas, nbrareas,
        W1, b1, A2, Ab2, out);
}

// round 10
// speedup vs baseline: 1.8061x; 1.0967x over previous
#include <cuda_runtime.h>
#include <cuda_fp16.h>
#include <math.h>
#include <stdint.h>

#define NPTS   30000
#define NV     4
#define SNB    6
#define PPT    18                  // points per tile (18*7 = 126 rows + 2 pad)
#define MROWS  128
#define TILES_MAIN 1667            // ceil(30000/18)
#define GRIDX  37
#define EP_ROWS 128
#define EP_TILES 235
#define EPB    9216                // 18 points * 512 B ep bytes per tile

typedef unsigned long long ull;

// ---------------- device scratch (allocation-free) ----------------
__device__ __align__(16) unsigned char g_Mt[NV * 131072];   // M^T fp16, swizzled [n][k] 512B rows
__device__ __align__(16) unsigned char g_Ang[NV * 98304];   // A1ng^T fp16, swizzled [h][i] 384B rows
__device__ float    g_C[NV * 256];
__device__ uint32_t g_ep[NV * NPTS * 128];                  // enc_pre half2 pairs

// ---------------- helpers ----------------
__device__ __forceinline__ uint32_t smem_u32(const void* p) {
    uint32_t a;
    asm("{ .reg .u64 t; cvta.to.shared.u64 t, %1; cvt.u32.u64 %0, t; }" : "=r"(a) : "l"(p));
    return a;
}
__device__ __forceinline__ void ldsm_x4(uint32_t r[4], uint32_t addr) {
    asm volatile("ldmatrix.sync.aligned.m8n8.x4.shared.b16 {%0,%1,%2,%3}, [%4];"
                 : "=r"(r[0]), "=r"(r[1]), "=r"(r[2]), "=r"(r[3]) : "r"(addr));
}
__device__ __forceinline__ void mma_16816(float c[4], const uint32_t a[4],
                                          uint32_t b0, uint32_t b1) {
    asm volatile("mma.sync.aligned.m16n8k16.row.col.f32.f16.f16.f32 "
                 "{%0,%1,%2,%3}, {%4,%5,%6,%7}, {%8,%9}, {%0,%1,%2,%3};"
                 : "+f"(c[0]), "+f"(c[1]), "+f"(c[2]), "+f"(c[3])
                 : "r"(a[0]), "r"(a[1]), "r"(a[2]), "r"(a[3]), "r"(b0), "r"(b1));
}
__device__ __forceinline__ ull pk2(float x, float y) {
    ull r; asm("mov.b64 %0, {%1, %2};" : "=l"(r) : "f"(x), "f"(y)); return r;
}
__device__ __forceinline__ void unpk2(ull p, float& x, float& y) {
    asm("mov.b64 {%0, %1}, %2;" : "=f"(x), "=f"(y) : "l"(p));
}
__device__ __forceinline__ void fma2(ull& d, ull a, ull b) {
    asm("fma.rn.f32x2 %0, %1, %2, %0;" : "+l"(d) : "l"(a), "l"(b));
}
__device__ __forceinline__ uint32_t f22u(float a, float b) {
    __half2 h = __floats2half2_rn(a, b);
    return *reinterpret_cast<uint32_t*>(&h);
}
__device__ __forceinline__ void cp16(uint32_t dst, const void* src) {
    asm volatile("cp.async.cg.shared.global [%0], [%1], 16;" :: "r"(dst), "l"(src));
}
__device__ __forceinline__ void cp_commit() { asm volatile("cp.async.commit_group;" ::: "memory"); }
__device__ __forceinline__ void cp_wait0()  { asm volatile("cp.async.wait_group 0;" ::: "memory"); }

// swizzled byte offsets: 16B-unit index XOR (row&7)
__device__ __forceinline__ uint32_t swz512(int r, int k) {
    return (uint32_t)(r * 512 + ((((k >> 3) ^ (r & 7))) << 4) + (k & 7) * 2);
}
__device__ __forceinline__ uint32_t swz384(int r, int k) {
    return (uint32_t)(r * 384 + ((((k >> 3) ^ (r & 7))) << 4) + (k & 7) * 2);
}

// ---------------- precompute kernels ----------------
__global__ void precompute_Mt(const float* __restrict__ W2, const float* __restrict__ A1) {
    int v = blockIdx.y, k = blockIdx.x, n = threadIdx.x;
    __shared__ float w2row[128];
    if (threadIdx.x < 128) w2row[threadIdx.x] = W2[(v * 256 + k) * 128 + threadIdx.x];
    __syncthreads();
    const float* a1 = A1 + (v * 320) * 256 + n;
    float acc = 0.f;
#pragma unroll 8
    for (int o = 0; o < 128; o++) acc += w2row[o] * a1[o * 256];
    *(__half*)(g_Mt + v * 131072 + swz512(n, k)) = __float2half(acc);
}

__global__ void precompute_C(const float* __restrict__ b2, const float* __restrict__ A1,
                             const float* __restrict__ Ab1) {
    int v = blockIdx.x, h = threadIdx.x;
    __shared__ float b2s[128];
    if (threadIdx.x < 128) b2s[threadIdx.x] = b2[v * 128 + threadIdx.x];
    __syncthreads();
    float acc = Ab1[v * 256 + h];
#pragma unroll 8
    for (int o = 0; o < 128; o++) acc += b2s[o] * A1[(v * 320 + o) * 256 + h];
    g_C[v * 256 + h] = acc;
}

__global__ void precompute_Ang(const float* __restrict__ A1) {
    int b = blockIdx.x;
    int v = b / 192, i = b % 192, h = threadIdx.x;
    *(__half*)(g_Ang + v * 98304 + swz384(h, i)) =
        __float2half(A1[(v * 320 + 128 + i) * 256 + h]);
}

// ---------------- ep prepass ----------------
#define E_B 0
#define E_A 98304
#define E_C 147456
#define EP_SMEM 148480

__global__ void __launch_bounds__(1024, 1)
ep_kernel(const float* __restrict__ encN, const float* __restrict__ encG) {
    extern __shared__ unsigned char smem[];
    const uint32_t sb = smem_u32(smem);
    const int tid = threadIdx.x, wid = tid >> 5, lane = tid & 31;
    const int v = blockIdx.y;
    const int wm = wid & 3, wn = wid >> 2;

    {
        const float4* src = (const float4*)(g_Ang + v * 98304);
        float4* dst = (float4*)(smem + E_B);
        for (int i = tid; i < 6144; i += 1024) dst[i] = src[i];
    }
    float* sC = (float*)(smem + E_C);
    if (tid < 256) sC[tid] = g_C[v * 256 + tid];
    __syncthreads();

    const int arow0 = wm * 32 + (lane & 15), arow1 = arow0 + 16;
    const uint32_t xc  = (uint32_t)(lane & 7) << 4;
    const uint32_t aT0 = sb + E_A + arow0 * 384;
    const uint32_t aT1 = sb + E_A + arow1 * 384;
    const uint32_t s16a = (uint32_t)(lane >> 4) * 16;
    const uint32_t s16b4 = (uint32_t)((lane >> 3) & 1) * 16;
    // B x4 bases: ntp covers nt={2ntp, 2ntp+1}; lane>>4 selects which nt of the pair
    uint32_t bX4[2];
#pragma unroll
    for (int ntp = 0; ntp < 2; ntp++)
        bX4[ntp] = sb + E_B + (uint32_t)(wn * 32 + ntp * 16 + ((lane >> 4) << 3) + (lane & 7)) * 384;
    const int l4 = lane >> 2, l2 = (lane & 3) * 2;

    for (int t = blockIdx.x; t < EP_TILES; t += GRIDX) {
        const int n0 = t * EP_ROWS;
        for (int i = tid; i < 12288; i += 1024) {
            int r = i / 96, kk = (i % 96) * 2, n = n0 + r;
            float e0 = 0.f, e1 = 0.f;
            if (n < NPTS) {
                if (kk < 128) { e0 = encN[n * 128 + kk];      e1 = encN[n * 128 + kk + 1]; }
                else          { e0 = encG[n * 64 + kk - 128]; e1 = encG[n * 64 + kk - 127]; }
            }
            *(uint32_t*)(smem + E_A + swz384(r, kk)) = f22u(e0, e1);
        }
        __syncthreads();

        float acc[2][4][4];
#pragma unroll
        for (int mt = 0; mt < 2; mt++)
#pragma unroll
            for (int nt = 0; nt < 4; nt++)
#pragma unroll
                for (int q = 0; q < 4; q++) acc[mt][nt][q] = 0.f;

#pragma unroll
        for (int ks = 0; ks < 12; ks++) {
            const uint32_t offA = ((uint32_t)ks * 32 + s16a) ^ xc;
            const uint32_t offB = ((uint32_t)ks * 32 + s16b4) ^ xc;
            uint32_t a0[4], a1[4];
            ldsm_x4(a0, aT0 + offA);
            ldsm_x4(a1, aT1 + offA);
#pragma unroll
            for (int ntp = 0; ntp < 2; ntp++) {
                uint32_t b[4];
                ldsm_x4(b, bX4[ntp] + offB);
                mma_16816(acc[0][2 * ntp],     a0, b[0], b[1]);
                mma_16816(acc[1][2 * ntp],     a1, b[0], b[1]);
                mma_16816(acc[0][2 * ntp + 1], a0, b[2], b[3]);
                mma_16816(acc[1][2 * ntp + 1], a1, b[2], b[3]);
            }
        }

#pragma unroll
        for (int mt = 0; mt < 2; mt++)
#pragma unroll
            for (int x = 0; x < 2; x++) {
                int row = wm * 32 + mt * 16 + x * 8 + l4;
                int n = n0 + row;
                if (n < NPTS) {
                    uint32_t* dst = &g_ep[(v * NPTS + n) * 128];
#pragma unroll
                    for (int nt = 0; nt < 4; nt++) {
                        int col = wn * 32 + nt * 8 + l2;
                        dst[col >> 1] = f22u(acc[mt][nt][2 * x] + sC[col],
                                             acc[mt][nt][2 * x + 1] + sC[col + 1]);
                    }
                }
            }
        __syncthreads();
    }
}

// ---------------- main fused kernel: 512 threads, 18 pts/tile ----------------
#define M_B   0
#define M_A   131072
#define M_EP  196608          // 2 x 9216
#define M_W1  215040
#define M_B1  222208
#define M_A2  223232
#define M_XF  224256
#define M_INV 228352          // 18*6 floats
#define M_ROW 228800          // 128 x 4 floats
#define MAIN_SMEM 230848

__global__ void __launch_bounds__(512, 1)
main_kernel(const float* __restrict__ centers,  const float* __restrict__ nbrs,
            const float* __restrict__ norms,    const float* __restrict__ nbrnorms,
            const float* __restrict__ areas,    const float* __restrict__ nbrareas,
            const float* __restrict__ W1,       const float* __restrict__ b1,
            const float* __restrict__ A2,       const float* __restrict__ Ab2,
            float* __restrict__ out) {
    extern __shared__ unsigned char smem[];
    const uint32_t sb = smem_u32(smem);
    const int tid = threadIdx.x, wid = tid >> 5, lane = tid & 31;
    const int v = blockIdx.y;
    const int wm = wid & 3, wn = wid >> 2;       // 4 m-warps x 4 n-warps, warp tile 32x64

    float* sW1  = (float*)(smem + M_W1);
    float* sB1  = (float*)(smem + M_B1);
    float* sA2  = (float*)(smem + M_A2);
    float* sXF  = (float*)(smem + M_XF);
    float* sInv = (float*)(smem + M_INV);
    float* sRow = (float*)(smem + M_ROW);

    { // resident B = M^T (128 KB, swizzled)
        const float4* src = (const float4*)(g_Mt + v * 131072);
        float4* dst = (float4*)(smem + M_B);
        for (int i = tid; i < 8192; i += 512) dst[i] = src[i];
    }
    if (tid < 256) { sA2[tid] = A2[v * 256 + tid]; sB1[tid] = b1[v * 256 + tid]; }
    for (int i = tid; i < 7 * 256; i += 512) sW1[i] = W1[v * 7 * 256 + i];
    const float Ab2v = Ab2[v];

    // ---- prologue: stage xf + ep for first tile ----
    const int t0 = blockIdx.x;
    if (tid < MROWS) {
        float f[7];
#pragma unroll
        for (int j = 0; j < 7; j++) f[j] = 0.f;
        if (tid < 126) {
            const int p = tid / 7, i = tid - p * 7, n = t0 * PPT + p;
            if (n < NPTS) {
                if (i == 0) {
                    f[0] = centers[n * 3 + 0]; f[1] = centers[n * 3 + 1]; f[2] = centers[n * 3 + 2];
                    f[3] = norms[n * 3 + 0];   f[4] = norms[n * 3 + 1];   f[5] = norms[n * 3 + 2];
                    f[6] = __logf(areas[n]) * 0.1f;
                } else {
                    int s = i - 1, base = (n * SNB + s) * 3;
                    f[0] = nbrs[base + 0] + 1e-6f;     f[1] = nbrs[base + 1] + 1e-6f;     f[2] = nbrs[base + 2] + 1e-6f;
                    f[3] = nbrnorms[base + 0] + 1e-6f; f[4] = nbrnorms[base + 1] + 1e-6f; f[5] = nbrnorms[base + 2] + 1e-6f;
                    f[6] = __logf(nbrareas[n * SNB + s]) * 0.1f + 1e-6f;
                }
            }
        }
#pragma unroll
        for (int j = 0; j < 7; j++) sXF[tid * 8 + j] = f[j];
        sXF[tid * 8 + 7] = 0.f;
    }
    {
        const size_t base = (size_t)(v * NPTS + t0 * PPT) * 512;
        for (int i = tid; i < 576; i += 512)
            if (t0 * PPT + (i >> 5) < NPTS)
                cp16(sb + M_EP + i * 16, (const unsigned char*)g_ep + base + (size_t)i * 16);
    }
    cp_commit();
    cp_wait0();
    __syncthreads();

    // lane-constant LDSM address terms
    const int arow = wm * 32 + (lane & 15);
    const uint32_t aT0 = sb + M_A + arow * 512;
    const uint32_t aT1 = aT0 + 16 * 512;
    const uint32_t xc  = (uint32_t)(lane & 7) << 4;
    const uint32_t s16a = (uint32_t)(lane >> 4) * 16;
    const uint32_t s16b4 = (uint32_t)((lane >> 3) & 1) * 16;
    const uint32_t bX4 = sb + M_B + (uint32_t)(wn * 64 + ((lane >> 4) << 3) + (lane & 7)) * 512;
    const int l4 = lane >> 2, l2 = (lane & 3) * 2;

    int ping = 0;
    for (int t = t0; t < TILES_MAIN; t += GRIDX) {
        const int n0p = t * PPT;
        const int tn = t + GRIDX;
        const bool nv_ok = (tn < TILES_MAIN);

        // ---- prefetch next tile's ep ----
        if (nv_ok) {
            const size_t base = (size_t)(v * NPTS + tn * PPT) * 512;
            const uint32_t dst0 = sb + M_EP + (ping ^ 1) * EPB;
            for (int i = tid; i < 576; i += 512)
                if (tn * PPT + (i >> 5) < NPTS)
                    cp16(dst0 + i * 16, (const unsigned char*)g_ep + base + (size_t)i * 16);
        }
        cp_commit();

        // ---- inverse distance ----
        if (tid < 126) {
            const int p = tid / 7, i = tid - p * 7;
            if (i >= 1) {
                float d2 = 0.f;
#pragma unroll
                for (int j = 0; j < 7; j++) {
                    float d = sXF[(p * 7) * 8 + j] - sXF[tid * 8 + j];
                    d2 += d * d;
                }
                sInv[p * 6 + (i - 1)] = rsqrtf(d2);
            }
        }

        // ---- R = relu(x@W1+b1) -> fp16 swizzled A ----
        {
            const int r = tid >> 2, q = tid & 3;
            ull xp[7];
#pragma unroll
            for (int j = 0; j < 7; j++) { float x = sXF[r * 8 + j]; xp[j] = pk2(x, x); }
#pragma unroll
            for (int hf = 0; hf < 2; hf++) {
                const int k0 = q * 64 + hf * 32;
                ull acc[16];
#pragma unroll
                for (int m = 0; m < 16; m++) acc[m] = *(const ull*)(sB1 + k0 + 2 * m);
#pragma unroll
                for (int j = 0; j < 7; j++) {
                    const ull* wp = (const ull*)(sW1 + j * 256 + k0);
#pragma unroll
                    for (int m = 0; m < 16; m++) fma2(acc[m], xp[j], wp[m]);
                }
#pragma unroll
                for (int g = 0; g < 4; g++) {
                    uint32_t h[4];
#pragma unroll
                    for (int qq = 0; qq < 4; qq++) {
                        float a, b; unpk2(acc[g * 4 + qq], a, b);
                        h[qq] = f22u(fmaxf(a, 0.f), fmaxf(b, 0.f));
                    }
                    uint32_t u = (uint32_t)(((k0 >> 3) + g) ^ (r & 7));
                    *(uint4*)(smem + M_A + r * 512 + (u << 4)) = make_uint4(h[0], h[1], h[2], h[3]);
                }
            }
        }
        __syncthreads();

        // ---- MMA mainloop: Z = A @ B^T (128x256x256), A prefetch + B x4 ----
        float acc[2][8][4];
#pragma unroll
        for (int mt = 0; mt < 2; mt++)
#pragma unroll
            for (int nt = 0; nt < 8; nt++)
#pragma unroll
                for (int q = 0; q < 4; q++) acc[mt][nt][q] = 0.f;

        uint32_t a0[4], a1[4];
        {
            uint32_t offA = s16a ^ xc;
            ldsm_x4(a0, aT0 + offA);
            ldsm_x4(a1, aT1 + offA);
        }
#pragma unroll
        for (int ks = 0; ks < 16; ks++) {
            const uint32_t offB = ((uint32_t)ks * 32 + s16b4) ^ xc;
            uint32_t na0[4], na1[4];
            if (ks < 15) {
                uint32_t offA = ((uint32_t)(ks + 1) * 32 + s16a) ^ xc;
                ldsm_x4(na0, aT0 + offA);
                ldsm_x4(na1, aT1 + offA);
            }
#pragma unroll
            for (int ntp = 0; ntp < 4; ntp++) {
                uint32_t b[4];
                ldsm_x4(b, bX4 + (uint32_t)ntp * 8192 + offB);
                mma_16816(acc[0][2 * ntp],     a0, b[0], b[1]);
                mma_16816(acc[1][2 * ntp],     a1, b[0], b[1]);
                mma_16816(acc[0][2 * ntp + 1], a0, b[2], b[3]);
                mma_16816(acc[1][2 * ntp + 1], a1, b[2], b[3]);
            }
            if (ks < 15) {
#pragma unroll
                for (int q = 0; q < 4; q++) { a0[q] = na0[q]; a1[q] = na1[q]; }
            }
        }

        // ---- epilogue: relu(Z+ep).A2 partials ----
        const uint32_t* sEPc = (const uint32_t*)(smem + M_EP + ping * EPB);
#pragma unroll
        for (int mt = 0; mt < 2; mt++)
#pragma unroll
            for (int x = 0; x < 2; x++) {
                int row = wm * 32 + mt * 16 + x * 8 + l4;
                int p = row / 7;               // 18 pts per tile; rows 126-127 read pad (ignored)
                float s = 0.f;
#pragma unroll
                for (int nt = 0; nt < 8; nt++) {
                    int col = wn * 64 + nt * 8 + l2;
                    __half2 ev = *(__half2*)&sEPc[p * 128 + (col >> 1)];
                    float z0 = acc[mt][nt][2 * x]     + __low2float(ev);
                    float z1 = acc[mt][nt][2 * x + 1] + __high2float(ev);
                    s = fmaf(fmaxf(z0, 0.f), sA2[col], s);
                    s = fmaf(fmaxf(z1, 0.f), sA2[col + 1], s);
                }
                s += __shfl_xor_sync(0xffffffffu, s, 1);
                s += __shfl_xor_sync(0xffffffffu, s, 2);
                if ((lane & 3) == 0) sRow[row * 4 + wn] = s;
            }
        __syncthreads();

        // ---- finalize output (18 points) ----
        if (tid < PPT && n0p + tid < NPTS) {
            float num = 0.f, den = 0.f, sc = 0.f;
#pragma unroll
            for (int i = 0; i < 7; i++) {
                float s = Ab2v;
                const float* rp = &sRow[(tid * 7 + i) * 4];
#pragma unroll
                for (int w = 0; w < 4; w++) s += rp[w];
                if (i == 0) sc = s;
                else {
                    float iv = sInv[tid * 6 + (i - 1)];
                    num = fmaf(s, iv, num);
                    den += iv;
                }
            }
            out[(n0p + tid) * NV + v] = 0.5f * sc + 0.5f * num / den;
        }

        // ---- restage next tile features ----
        if (tid < MROWS && nv_ok) {
            float f[7];
#pragma unroll
            for (int j = 0; j < 7; j++) f[j] = 0.f;
            if (tid < 126) {
                const int p = tid / 7, i = tid - p * 7, n = tn * PPT + p;
                if (n < NPTS) {
                    if (i == 0) {
                        f[0] = centers[n * 3 + 0]; f[1] = centers[n * 3 + 1]; f[2] = centers[n * 3 + 2];
                        f[3] = norms[n * 3 + 0];   f[4] = norms[n * 3 + 1];   f[5] = norms[n * 3 + 2];
                        f[6] = __logf(areas[n]) * 0.1f;
                    } else {
                        int s = i - 1, base = (n * SNB + s) * 3;
                        f[0] = nbrs[base + 0] + 1e-6f;     f[1] = nbrs[base + 1] + 1e-6f;     f[2] = nbrs[base + 2] + 1e-6f;
                        f[3] = nbrnorms[base + 0] + 1e-6f; f[4] = nbrnorms[base + 1] + 1e-6f; f[5] = nbrnorms[base + 2] + 1e-6f;
                        f[6] = __logf(nbrareas[n * SNB + s]) * 0.1f + 1e-6f;
                    }
                }
            }
#pragma unroll
            for (int j = 0; j < 7; j++) sXF[tid * 8 + j] = f[j];
            sXF[tid * 8 + 7] = 0.f;
        }
        cp_wait0();
        __syncthreads();
        ping ^= 1;
    }
}

// ---------------- launch ----------------
extern "C" void kernel_launch(void* const* d_in, const int* in_sizes, int n_in,
                              void* d_out, int out_size) {
    const float* centers  = (const float*)d_in[0];
    const float* encG     = (const float*)d_in[1];
    const float* encN     = (const float*)d_in[2];
    const float* nbrs     = (const float*)d_in[3];
    const float* norms    = (const float*)d_in[4];
    const float* nbrnorms = (const float*)d_in[5];
    const float* areas    = (const float*)d_in[6];
    const float* nbrareas = (const float*)d_in[7];
    const float* W1  = (const float*)d_in[10];
    const float* b1  = (const float*)d_in[11];
    const float* W2  = (const float*)d_in[12];
    const float* b2  = (const float*)d_in[13];
    const float* A1  = (const float*)d_in[14];
    const float* Ab1 = (const float*)d_in[15];
    const float* A2  = (const float*)d_in[16];
    const float* Ab2 = (const float*)d_in[17];
    float* out = (float*)d_out;

    cudaFuncSetAttribute(ep_kernel,   cudaFuncAttributeMaxDynamicSharedMemorySize, EP_SMEM);
    cudaFuncSetAttribute(main_kernel, cudaFuncAttributeMaxDynamicSharedMemorySize, MAIN_SMEM);

    precompute_Mt<<<dim3(256, NV), 256>>>(W2, A1);
    precompute_C<<<NV, 256>>>(b2, A1, Ab1);
    precompute_Ang<<<NV * 192, 256>>>(A1);
    ep_kernel<<<dim3(GRIDX, NV), 1024, EP_SMEM>>>(encN, encG);
    main_kernel<<<dim3(GRIDX, NV), 512, MAIN_SMEM>>>(
        centers, nbrs, norms, nbrnorms, areas, nbrareas,
        W1, b1, A2, Ab2, out);
}